// round 3
// baseline (speedup 1.0000x reference)
#include <cuda_runtime.h>

// Problem shape (fixed by setup_inputs): BATCH=16384, P=16, D=2048
#define BATCH   16384
#define PNUM    16
#define DIM     2048
#define NGROUP  (BATCH / PNUM)     // 1024
#define D4      (DIM / 4)          // 512 float4 per row
#define THREADS 256
#define RUNROLL 4                  // rows per load batch

// Device-global scratch (statically zero-initialized; finalizing block resets
// it each run -> deterministic across graph replays, no init launch).
__device__ double        g_acc   = 0.0;
__device__ unsigned int  g_count = 0u;

__global__ __launch_bounds__(THREADS) void fl_fused_kernel(const float4* __restrict__ f,
                                                           float* __restrict__ out) {
    const int g = blockIdx.x;
    const float4* base = f + (size_t)g * PNUM * D4;

    const int c0 = threadIdx.x;            // column stream 0
    const int c1 = threadIdx.x + THREADS;  // column stream 1

    float ssq0 = 0.0f, ssq1 = 0.0f;                      // element^2 partials
    float4 cs0 = make_float4(0.f, 0.f, 0.f, 0.f);        // column sums, stream 0
    float4 cs1 = make_float4(0.f, 0.f, 0.f, 0.f);        // column sums, stream 1

    #pragma unroll
    for (int r = 0; r < PNUM; r += RUNROLL) {
        // Batch 8 independent loads up front for high MLP.
        float4 v[RUNROLL], w[RUNROLL];
        #pragma unroll
        for (int i = 0; i < RUNROLL; i++) v[i] = base[(r + i) * D4 + c0];
        #pragma unroll
        for (int i = 0; i < RUNROLL; i++) w[i] = base[(r + i) * D4 + c1];

        #pragma unroll
        for (int i = 0; i < RUNROLL; i++) {
            cs0.x += v[i].x; cs0.y += v[i].y; cs0.z += v[i].z; cs0.w += v[i].w;
            ssq0  += v[i].x * v[i].x + v[i].y * v[i].y + v[i].z * v[i].z + v[i].w * v[i].w;
            cs1.x += w[i].x; cs1.y += w[i].y; cs1.z += w[i].z; cs1.w += w[i].w;
            ssq1  += w[i].x * w[i].x + w[i].y * w[i].y + w[i].z * w[i].z + w[i].w * w[i].w;
        }
    }

    float scol = cs0.x * cs0.x + cs0.y * cs0.y + cs0.z * cs0.z + cs0.w * cs0.w
               + cs1.x * cs1.x + cs1.y * cs1.y + cs1.z * cs1.z + cs1.w * cs1.w;

    // Contribution to sum_g (B_g - A_g)
    double d = (double)((ssq0 + ssq1) - scol);

    // warp reduce
    #pragma unroll
    for (int o = 16; o; o >>= 1)
        d += __shfl_xor_sync(0xffffffffu, d, o);

    __shared__ double sh[THREADS / 32];
    if ((threadIdx.x & 31) == 0) sh[threadIdx.x >> 5] = d;
    __syncthreads();

    if (threadIdx.x == 0) {
        double b = 0.0;
        #pragma unroll
        for (int w2 = 0; w2 < THREADS / 32; w2++) b += sh[w2];
        atomicAdd(&g_acc, b);
        __threadfence();
        unsigned int ticket = atomicAdd(&g_count, 1u);
        if (ticket == NGROUP - 1u) {
            const double pairs = (double)PNUM * (PNUM - 1) / 2.0;  // 120
            double acc = g_acc;                                     // all adds visible
            out[0] = (float)(1.0 + acc / (2.0 * pairs * (double)NGROUP));
            // reset for next invocation / graph replay
            g_acc   = 0.0;
            g_count = 0u;
        }
    }
}

extern "C" void kernel_launch(void* const* d_in, const int* in_sizes, int n_in,
                              void* d_out, int out_size) {
    (void)in_sizes; (void)n_in; (void)out_size;
    const float4* f = (const float4*)d_in[0];
    float* out = (float*)d_out;
    fl_fused_kernel<<<NGROUP, THREADS>>>(f, out);
}

// round 4
// speedup vs baseline: 1.0748x; 1.0748x over previous
#include <cuda_runtime.h>

// Problem shape (fixed by setup_inputs): BATCH=16384, P=16, D=2048
#define BATCH   16384
#define PNUM    16
#define DIM     2048
#define NGROUP  (BATCH / PNUM)     // 1024
#define D4      (DIM / 4)          // 512 float4 per row
#define THREADS 256
#define NBLK    512                // CTAs; each handles GPB groups
#define GPB     (NGROUP / NBLK)    // 2 groups per block

// Device-global scratch (statically zero-initialized; finalizing block resets
// it each run -> deterministic across graph replays, no init launch).
__device__ double        g_acc   = 0.0;
__device__ unsigned int  g_count = 0u;

__global__ __launch_bounds__(THREADS) void fl_fused_kernel(const float4* __restrict__ f,
                                                           float* __restrict__ out) {
    const int c0 = threadIdx.x;            // column stream 0
    const int c1 = threadIdx.x + THREADS;  // column stream 1

    double d = 0.0;  // per-thread contribution to sum_g (B_g - A_g)

    #pragma unroll
    for (int gi = 0; gi < GPB; gi++) {
        const int g = blockIdx.x + gi * NBLK;
        const float4* base = f + (size_t)g * PNUM * D4;

        float  ssq0 = 0.0f, ssq1 = 0.0f;
        float4 cs0 = make_float4(0.f, 0.f, 0.f, 0.f);
        float4 cs1 = make_float4(0.f, 0.f, 0.f, 0.f);

        #pragma unroll
        for (int r = 0; r < PNUM; r++) {
            float4 v = base[r * D4 + c0];
            float4 w = base[r * D4 + c1];
            cs0.x += v.x; cs0.y += v.y; cs0.z += v.z; cs0.w += v.w;
            ssq0  += v.x * v.x + v.y * v.y + v.z * v.z + v.w * v.w;
            cs1.x += w.x; cs1.y += w.y; cs1.z += w.z; cs1.w += w.w;
            ssq1  += w.x * w.x + w.y * w.y + w.z * w.z + w.w * w.w;
        }

        float scol = cs0.x * cs0.x + cs0.y * cs0.y + cs0.z * cs0.z + cs0.w * cs0.w
                   + cs1.x * cs1.x + cs1.y * cs1.y + cs1.z * cs1.z + cs1.w * cs1.w;

        d += (double)((ssq0 + ssq1) - scol);
    }

    // warp reduce
    #pragma unroll
    for (int o = 16; o; o >>= 1)
        d += __shfl_xor_sync(0xffffffffu, d, o);

    __shared__ double sh[THREADS / 32];
    if ((threadIdx.x & 31) == 0) sh[threadIdx.x >> 5] = d;
    __syncthreads();

    if (threadIdx.x == 0) {
        double b = 0.0;
        #pragma unroll
        for (int w2 = 0; w2 < THREADS / 32; w2++) b += sh[w2];
        atomicAdd(&g_acc, b);
        __threadfence();
        unsigned int ticket = atomicAdd(&g_count, 1u);
        if (ticket == NBLK - 1u) {
            const double pairs = (double)PNUM * (PNUM - 1) / 2.0;  // 120
            double acc = g_acc;                                     // all adds visible
            out[0] = (float)(1.0 + acc / (2.0 * pairs * (double)NGROUP));
            // reset for next invocation / graph replay
            g_acc   = 0.0;
            g_count = 0u;
        }
    }
}

extern "C" void kernel_launch(void* const* d_in, const int* in_sizes, int n_in,
                              void* d_out, int out_size) {
    (void)in_sizes; (void)n_in; (void)out_size;
    const float4* f = (const float4*)d_in[0];
    float* out = (float*)d_out;
    fl_fused_kernel<<<NBLK, THREADS>>>(f, out);
}